// round 15
// baseline (speedup 1.0000x reference)
#include <cuda_runtime.h>

#define B_    16384
#define T_    64
#define NB    4          // batch elems per CTA (8 groups: 4 elems x 2 dirs)
#define NTHR  128        // 8 groups x 16 lanes; 4 warps; 3 CTAs/SM -> 3 warps/SMSP
#define EPAD  2052       // floats per elem tile: 64*32 + pad, 16B-aligned

typedef unsigned long long u64;

#define L2E 1.4426950408889634f

// Small smem: activations + n-gate weight stream + biases. r/z weights live
// in per-thread registers (loaded from global once per layer).
struct __align__(16) Smem {
    u64   win[2][16][16];         // n-gate input weights  [dir][u][k-pair]
    u64   whn[2][16][8];          // n-gate recur weights  [dir][u][k-pair]
    float actA[NB][EPAD];
    float actB[NB][EPAD];
    float bR[2][16], bZ[2][16], bNX[2][16], bNH[2][16];
    float wcw[4][32];
    float wcb[4];
};

__device__ __forceinline__ u64 pack2(float lo, float hi) {
    u64 r; asm("mov.b64 %0, {%1, %2};" : "=l"(r) : "f"(lo), "f"(hi)); return r;
}
__device__ __forceinline__ void unpack2(u64 d, float& lo, float& hi) {
    asm("mov.b64 {%0, %1}, %2;" : "=f"(lo), "=f"(hi) : "l"(d));
}
__device__ __forceinline__ u64 ffma2(u64 a, u64 b, u64 c) {
    u64 d; asm("fma.rn.f32x2 %0, %1, %2, %3;" : "=l"(d) : "l"(a), "l"(b), "l"(c)); return d;
}
__device__ __forceinline__ float hadd(u64 v) {
    float lo, hi; unpack2(v, lo, hi); return lo + hi;
}
__device__ __forceinline__ float ex2(float x) {
    float r; asm("ex2.approx.ftz.f32 %0, %1;" : "=f"(r) : "f"(x)); return r;
}
__device__ __forceinline__ float rcp(float x) {
    float r; asm("rcp.approx.ftz.f32 %0, %1;" : "=f"(r) : "f"(x)); return r;
}
// s pre-scaled by log2e: sigmoid(x) = 1/(1+2^-s)
__device__ __forceinline__ float sigm2(float s) {
    return rcp(1.f + ex2(-s));
}
// s pre-scaled by 2*log2e: tanh(x) = sign * (1-2^-|s|)/(1+2^-|s|)
__device__ __forceinline__ float tanh2(float s) {
    float a = fabsf(s);
    float e = ex2(-a);
    float t = (1.f - e) * rcp(1.f + e);
    return copysignf(t, s);
}

// Stage n-gate weights (pre-scaled by 2*log2e) + biases into smem.
// r/z weights are NOT staged — each thread loads its own rows to registers.
template <int F, int KP>
__device__ __forceinline__ void stage_layer(Smem* s,
        const float* __restrict__ Wi, const float* __restrict__ Wh,
        const float* __restrict__ bi, const float* __restrict__ bh,
        int tid)
{
    const float sc = 2.f * L2E;
    for (int i = tid; i < 2 * 16 * KP; i += NTHR) {
        int d = i / (16 * KP); int r = i - d * (16 * KP);
        int uu = r / KP, kp = r - uu * KP;
        const float* w = Wi + ((size_t)d * 48 + 32 + uu) * F;
        float lo = w[2 * kp] * sc;
        float hi = (2 * kp + 1 < F) ? w[2 * kp + 1] * sc : 0.f;
        s->win[d][uu][kp] = pack2(lo, hi);
    }
    for (int i = tid; i < 2 * 16 * 8; i += NTHR) {
        int d = i >> 7; int r = i & 127;
        int uu = r >> 3, kp = r & 7;
        const float* w = Wh + ((size_t)d * 48 + 32 + uu) * 16;
        s->whn[d][uu][kp] = pack2(w[2 * kp] * sc, w[2 * kp + 1] * sc);
    }
    for (int i = tid; i < 2 * 16; i += NTHR) {
        int d = i >> 4, uu = i & 15;
        s->bR[d][uu]  = (bi[d * 48 + uu]      + bh[d * 48 + uu])      * L2E;
        s->bZ[d][uu]  = (bi[d * 48 + 16 + uu] + bh[d * 48 + 16 + uu]) * L2E;
        s->bNX[d][uu] = bi[d * 48 + 32 + uu] * sc;
        s->bNH[d][uu] = bh[d * 48 + 32 + uu] * sc;
    }
}

// One bidirectional GRU layer. Lane u of a 16-lane group owns hidden unit u
// of ONE chain. r/z weights in registers (loaded from global, scaled);
// n-gate weights streamed from smem (broadcast LDS.128). Recurrence h
// gathered via width-16 shfl. 3 warps/SMSP (3 CTAs/SM) interleave through
// each other's gate-tail stalls with zero added instructions per step.
template <int KP, int F>
__device__ __forceinline__ void run_layer(Smem* s,
        const float (*rd)[EPAD], float (*wr)[EPAD],
        const float* __restrict__ Wi, const float* __restrict__ Wh,
        int elem, int dir, int u)
{
    // r/z input weights: global -> regs, pre-scaled by log2e
    u64 wir[KP], wiz[KP];
    {
        const float* wrr = Wi + ((size_t)dir * 48 + u) * F;
        const float* wrz = Wi + ((size_t)dir * 48 + 16 + u) * F;
#pragma unroll
        for (int k = 0; k < KP; k++) {
            float rl = wrr[2 * k] * L2E;
            float rh = (2 * k + 1 < F) ? wrr[2 * k + 1] * L2E : 0.f;
            float zl = wrz[2 * k] * L2E;
            float zh = (2 * k + 1 < F) ? wrz[2 * k + 1] * L2E : 0.f;
            wir[k] = pack2(rl, rh);
            wiz[k] = pack2(zl, zh);
        }
    }
    // r/z recurrent weights: global -> regs, pre-scaled
    u64 whr[8], whz[8];
    {
        const float* whrp = Wh + ((size_t)dir * 48 + u) * 16;
        const float* whzp = Wh + ((size_t)dir * 48 + 16 + u) * 16;
#pragma unroll
        for (int k = 0; k < 8; k++) {
            whr[k] = pack2(whrp[2 * k] * L2E, whrp[2 * k + 1] * L2E);
            whz[k] = pack2(whzp[2 * k] * L2E, whzp[2 * k + 1] * L2E);
        }
    }
    const float br  = s->bR[dir][u],  bz  = s->bZ[dir][u];
    const float bnx = s->bNX[dir][u], bnh = s->bNH[dir][u];
    const ulonglong2* __restrict__ winp = (const ulonglong2*)&s->win[dir][u][0];
    const ulonglong2* __restrict__ whnp = (const ulonglong2*)&s->whn[dir][u][0];
    const int wcol = dir * 16 + u;
    const int stp  = dir ? -1 : 1;

    float h;

    // x-gemm at time t (biases folded into accumulator init)
    auto xgemm = [&](int t, u64& ar, u64& az, u64& an) {
        ar = pack2(br, 0.f); az = pack2(bz, 0.f); an = pack2(bnx, 0.f);
        const ulonglong2* xp = (const ulonglong2*)&rd[elem][t * 32];
#pragma unroll
        for (int k = 0; k < KP / 2; k++) {
            ulonglong2 xv = xp[k];
            ulonglong2 wn = winp[k];
            ar = ffma2(wir[2*k],   xv.x, ar);
            az = ffma2(wiz[2*k],   xv.x, az);
            an = ffma2(wn.x,       xv.x, an);
            ar = ffma2(wir[2*k+1], xv.y, ar);
            az = ffma2(wiz[2*k+1], xv.y, az);
            an = ffma2(wn.y,       xv.y, an);
        }
    };

    int t = dir ? (T_ - 1) : 0;

    // ---- peeled first step (h == 0, no recurrence) ----
    {
        u64 ar, az, an;
        xgemm(t, ar, az, an);
        float r = sigm2(hadd(ar));
        float z = sigm2(hadd(az));
        float n = tanh2(fmaf(r, bnh, hadd(an)));
        h = fmaf(-z, n, n);                      // (1-z)*n
        wr[elem][t * 32 + wcol] = h;
    }
    t += stp;

#pragma unroll 1
    for (int ti = 1; ti < T_; ++ti) {
        u64 ar, az, an;
        xgemm(t, ar, az, an);
        // recurrence: gather group's h via shfl (width 16), n-weights from smem
        u64 anh = pack2(bnh, 0.f);
#pragma unroll
        for (int k = 0; k < 4; k++) {
            ulonglong2 wn = whnp[k];
            float h0 = __shfl_sync(0xffffffffu, h, 4 * k,     16);
            float h1 = __shfl_sync(0xffffffffu, h, 4 * k + 1, 16);
            float h2 = __shfl_sync(0xffffffffu, h, 4 * k + 2, 16);
            float h3 = __shfl_sync(0xffffffffu, h, 4 * k + 3, 16);
            u64 hv0 = pack2(h0, h1);
            u64 hv1 = pack2(h2, h3);
            ar  = ffma2(whr[2*k],   hv0, ar);
            az  = ffma2(whz[2*k],   hv0, az);
            anh = ffma2(wn.x,       hv0, anh);
            ar  = ffma2(whr[2*k+1], hv1, ar);
            az  = ffma2(whz[2*k+1], hv1, az);
            anh = ffma2(wn.y,       hv1, anh);
        }
        float r = sigm2(hadd(ar));
        float z = sigm2(hadd(az));
        float n = tanh2(fmaf(r, hadd(anh), hadd(an)));
        h = fmaf(z, h - n, n);                   // (1-z)*n + z*h
        wr[elem][t * 32 + wcol] = h;
        t += (ti == T_ - 1) ? 0 : stp;
    }
}

extern "C" __global__ void __launch_bounds__(NTHR, 3)
fused_gru(const float* __restrict__ x,
          const float* __restrict__ Wi1, const float* __restrict__ Wh1,
          const float* __restrict__ bi1, const float* __restrict__ bh1,
          const float* __restrict__ Wi5, const float* __restrict__ Wh5,
          const float* __restrict__ bi5, const float* __restrict__ bh5,
          const float* __restrict__ Wc,  const float* __restrict__ bc,
          float* __restrict__ out)
{
    extern __shared__ __align__(16) unsigned char smraw[];
    Smem* s = reinterpret_cast<Smem*>(smraw);

    const int tid   = threadIdx.x;
    const int u     = tid & 15;
    const int g     = tid >> 4;          // 8 groups; warp-uniform dir:
    const int dir   = g >> 2;            //  warps 0,1 -> dir 0; warps 2,3 -> dir 1
    const int elem  = g & 3;
    const int gbase = blockIdx.x * NB;

    // Stage layer-0 input x[B,T,3] into actA channels 0..3 (ch3 zeroed).
    for (int i = tid; i < NB * T_ * 4; i += NTHR) {
        int e = i >> 8; int r = i & 255; int t = r >> 2; int c = r & 3;
        float v = 0.f;
        if (c < 3)
            v = x[((size_t)(gbase + e)) * (T_ * 3) + t * 3 + c];
        s->actA[e][t * 32 + c] = v;
    }
    // Stage classifier weights once (unscaled).
    for (int i = tid; i < 128; i += NTHR) s->wcw[i >> 5][i & 31] = Wc[i];
    if (tid < 4) s->wcb[tid] = bc[tid];

    // Layer 0 (F=3, padded to 4 -> KP=2): actA -> actB
    stage_layer<3, 2>(s, Wi1, Wh1, bi1, bh1, tid);
    __syncthreads();
    run_layer<2, 3>(s, s->actA, s->actB, Wi1, Wh1, elem, dir, u);
    __syncthreads();

    // Layers 1..5 (F=32, KP=16), ping-pong. Final output lands in actA.
#pragma unroll 1
    for (int l = 0; l < 5; l++) {
        const float* Wi = Wi5 + (size_t)l * 3072;
        const float* Wh = Wh5 + (size_t)l * 1536;
        stage_layer<32, 16>(s, Wi, Wh,
                            bi5 + (size_t)l * 96, bh5 + (size_t)l * 96, tid);
        __syncthreads();
        if (l & 1) run_layer<16, 32>(s, s->actA, s->actB, Wi, Wh, elem, dir, u);
        else       run_layer<16, 32>(s, s->actB, s->actA, Wi, Wh, elem, dir, u);
        __syncthreads();
    }

    // Classifier + softmax, straight from smem to d_out (coalesced float4).
    for (int i = tid; i < NB * T_; i += NTHR) {
        int e = i >> 6, t = i & 63;
        const ulonglong2* yp = (const ulonglong2*)&s->actA[e][t * 32];
        const ulonglong2* w0 = (const ulonglong2*)&s->wcw[0][0];
        const ulonglong2* w1 = (const ulonglong2*)&s->wcw[1][0];
        const ulonglong2* w2 = (const ulonglong2*)&s->wcw[2][0];
        const ulonglong2* w3 = (const ulonglong2*)&s->wcw[3][0];
        u64 a0 = 0, a1 = 0, a2 = 0, a3 = 0;
#pragma unroll
        for (int k = 0; k < 8; k++) {
            ulonglong2 yv = yp[k];
            ulonglong2 c0 = w0[k], c1 = w1[k], c2 = w2[k], c3 = w3[k];
            a0 = ffma2(c0.x, yv.x, a0); a0 = ffma2(c0.y, yv.y, a0);
            a1 = ffma2(c1.x, yv.x, a1); a1 = ffma2(c1.y, yv.y, a1);
            a2 = ffma2(c2.x, yv.x, a2); a2 = ffma2(c2.y, yv.y, a2);
            a3 = ffma2(c3.x, yv.x, a3); a3 = ffma2(c3.y, yv.y, a3);
        }
        float l0 = hadd(a0) + s->wcb[0];
        float l1 = hadd(a1) + s->wcb[1];
        float l2 = hadd(a2) + s->wcb[2];
        float l3 = hadd(a3) + s->wcb[3];
        float m  = fmaxf(fmaxf(l0, l1), fmaxf(l2, l3));
        float e0 = __expf(l0 - m), e1 = __expf(l1 - m);
        float e2 = __expf(l2 - m), e3 = __expf(l3 - m);
        float rs = __fdividef(1.f, e0 + e1 + e2 + e3);
        float4 o = make_float4(e0 * rs, e1 * rs, e2 * rs, e3 * rs);
        reinterpret_cast<float4*>(out)[((size_t)(gbase + e)) * T_ + t] = o;
    }
}

extern "C" void kernel_launch(void* const* d_in, const int* in_sizes, int n_in,
                              void* d_out, int out_size)
{
    const float* x   = (const float*)d_in[0];
    const float* Wi1 = (const float*)d_in[1];
    const float* Wh1 = (const float*)d_in[2];
    const float* bi1 = (const float*)d_in[3];
    const float* bh1 = (const float*)d_in[4];
    const float* Wi5 = (const float*)d_in[5];
    const float* Wh5 = (const float*)d_in[6];
    const float* bi5 = (const float*)d_in[7];
    const float* bh5 = (const float*)d_in[8];
    const float* Wc  = (const float*)d_in[9];
    const float* bc  = (const float*)d_in[10];
    float* out = (float*)d_out;

    static bool once = []() {
        cudaFuncSetAttribute(fused_gru,
            cudaFuncAttributeMaxDynamicSharedMemorySize, (int)sizeof(Smem));
        return true;
    }();
    (void)once;

    fused_gru<<<B_ / NB, NTHR, sizeof(Smem)>>>(
        x, Wi1, Wh1, bi1, bh1, Wi5, Wh5, bi5, bh5, Wc, bc, out);
}

// round 16
// speedup vs baseline: 1.7801x; 1.7801x over previous
#include <cuda_runtime.h>
#include <cuda_fp16.h>

#define B_    16384
#define T_    64
#define NB    12
#define NTHR  128
#define BLK   8            // timesteps per XP phase (per direction)
#define NPH   8            // phases per layer = T_/BLK
#define EPADH 2056         // halves per elem tile (64*32 + 8 pad)
#define XPW   100          // xp row width (96 cols + 4 pad, bank skew)

typedef unsigned long long u64;
#define L2E 1.4426950408889634f

struct __align__(16) Smem {
    __half actA[NB][EPADH];        // fp16 activation tiles (ping)
    __half actB[NB][EPADH];        // (pong)
    float  xp[2][NB][BLK][XPW];    // gate preacts: [fwd/bwd][elem][t-in-blk][96]
    float  whi[96][33];            // Wi hi (tf32-valued, prescaled), padded
    float  wlo[96][33];            // Wi lo residual (tf32-valued)
    u64    wh[2][48][8];           // Wh f32x2 pairs, prescaled
    float  xpb[96];                // gate bias (GEMM epilogue), prescaled
    float  bNH[2][16];             // bh n-gate, prescaled
    float  wcw[4][32];
    float  wcb[4];
};

__device__ __forceinline__ u64 pack2(float lo, float hi) {
    u64 r; asm("mov.b64 %0, {%1, %2};" : "=l"(r) : "f"(lo), "f"(hi)); return r;
}
__device__ __forceinline__ void unpack2(u64 d, float& lo, float& hi) {
    asm("mov.b64 {%0, %1}, %2;" : "=f"(lo), "=f"(hi) : "l"(d));
}
__device__ __forceinline__ u64 ffma2(u64 a, u64 b, u64 c) {
    u64 d; asm("fma.rn.f32x2 %0, %1, %2, %3;" : "=l"(d) : "l"(a), "l"(b), "l"(c)); return d;
}
__device__ __forceinline__ float hadd(u64 v) {
    float lo, hi; unpack2(v, lo, hi); return lo + hi;
}
__device__ __forceinline__ float ex2(float x) {
    float r; asm("ex2.approx.ftz.f32 %0, %1;" : "=f"(r) : "f"(x)); return r;
}
__device__ __forceinline__ float rcp(float x) {
    float r; asm("rcp.approx.ftz.f32 %0, %1;" : "=f"(r) : "f"(x)); return r;
}
__device__ __forceinline__ float sigm2(float s) {       // s prescaled by log2e
    return rcp(1.f + ex2(-s));
}
__device__ __forceinline__ float tanh2(float s) {       // s prescaled by 2*log2e
    float a = fabsf(s);
    float e = ex2(-a);
    float t = (1.f - e) * rcp(1.f + e);
    return copysignf(t, s);
}
__device__ __forceinline__ unsigned cvt_tf32(float x) {
    unsigned r; asm("cvt.rna.tf32.f32 %0, %1;" : "=r"(r) : "f"(x)); return r;
}
__device__ __forceinline__ void mma_tf32(float& d0, float& d1, float& d2, float& d3,
                                         unsigned a0, unsigned a1, unsigned a2, unsigned a3,
                                         unsigned b0, unsigned b1) {
    asm volatile(
        "mma.sync.aligned.m16n8k8.row.col.f32.tf32.tf32.f32 "
        "{%0,%1,%2,%3}, {%4,%5,%6,%7}, {%8,%9}, {%0,%1,%2,%3};"
        : "+f"(d0), "+f"(d1), "+f"(d2), "+f"(d3)
        : "r"(a0), "r"(a1), "r"(a2), "r"(a3), "r"(b0), "r"(b1));
}

// Stage one layer: Wi -> tf32 hi/lo planes (prescaled), Wh -> f32x2 pairs,
// biases folded for GEMM epilogue (r/z include bh; n keeps bh separate).
template <int F>
__device__ __forceinline__ void stage_layer(Smem* s,
        const float* __restrict__ Wi, const float* __restrict__ Wh,
        const float* __restrict__ bi, const float* __restrict__ bh, int tid)
{
    for (int idx = tid; idx < 96 * 32; idx += NTHR) {
        int n = idx >> 5, k = idx & 31;
        int d = n / 48, gate = n - d * 48;
        float sc = (gate < 32) ? L2E : 2.f * L2E;
        float w = (k < F) ? Wi[((size_t)d * 48 + gate) * F + k] * sc : 0.f;
        float hi = __uint_as_float(cvt_tf32(w));
        s->whi[n][k] = hi;
        s->wlo[n][k] = __uint_as_float(cvt_tf32(w - hi));
    }
    for (int i = tid; i < 2 * 48 * 8; i += NTHR) {
        int d = i / 384; int r = i - d * 384;
        int row = r >> 3, kp = r & 7;
        float sc = (row < 32) ? L2E : 2.f * L2E;
        const float* w = Wh + ((size_t)d * 48 + row) * 16;
        s->wh[d][row][kp] = pack2(w[2 * kp] * sc, w[2 * kp + 1] * sc);
    }
    for (int i = tid; i < 96; i += NTHR) {
        int d = i / 48, gate = i - d * 48;
        if (gate < 32) {
            s->xpb[i] = (bi[d * 48 + gate] + bh[d * 48 + gate]) * L2E;
        } else {
            s->xpb[i] = bi[d * 48 + gate] * 2.f * L2E;
            s->bNH[d][gate - 32] = bh[d * 48 + gate] * 2.f * L2E;
        }
    }
}

// XP GEMM for one phase. Sub-block 0: fwd t in [8s,8s+8); sub 1: bwd t in
// [56-8s,64-8s). 12 M-tiles of 16 rows; warp w owns tiles 3w..3w+2.
// A = fp16 activations (exactly representable in tf32); W = hi+lo tf32.
template <int KT>
__device__ __forceinline__ void gemm_phase(Smem* s, const __half (*in)[EPADH],
                                           int sph, int warp, int lane)
{
    const int g = lane >> 2, tg = lane & 3;
#pragma unroll
    for (int i = 0; i < 3; i++) {
        const int mt  = warp * 3 + i;
        const int sub = (mt >= 6) ? 1 : 0;
        const int mt6 = mt - sub * 6;
        const int r0 = mt6 * 16 + g;
        const int r1 = r0 + 8;
        const int e0 = r0 >> 3, j0 = r0 & 7;
        const int e1 = r1 >> 3, j1 = r1 & 7;
        const int tb = sub ? (56 - 8 * sph) : (8 * sph);
        const int t0 = tb + j0, t1 = tb + j1;

        unsigned a[KT][4];
#pragma unroll
        for (int kt = 0; kt < KT; kt++) {
            int k0 = kt * 8 + tg;
            a[kt][0] = __float_as_uint(__half2float(in[e0][t0 * 32 + k0]));
            a[kt][1] = __float_as_uint(__half2float(in[e1][t1 * 32 + k0]));
            a[kt][2] = __float_as_uint(__half2float(in[e0][t0 * 32 + k0 + 4]));
            a[kt][3] = __float_as_uint(__half2float(in[e1][t1 * 32 + k0 + 4]));
        }
#pragma unroll 1
        for (int nt = 0; nt < 12; nt++) {
            const int n  = nt * 8 + g;
            const int c0 = nt * 8 + 2 * tg;
            float d0 = s->xpb[c0], d1 = s->xpb[c0 + 1];
            float d2 = d0, d3 = d1;
#pragma unroll
            for (int kt = 0; kt < KT; kt++) {
                int kb = kt * 8 + tg;
                unsigned bh0 = __float_as_uint(s->whi[n][kb]);
                unsigned bh1 = __float_as_uint(s->whi[n][kb + 4]);
                unsigned bl0 = __float_as_uint(s->wlo[n][kb]);
                unsigned bl1 = __float_as_uint(s->wlo[n][kb + 4]);
                mma_tf32(d0, d1, d2, d3, a[kt][0], a[kt][1], a[kt][2], a[kt][3], bh0, bh1);
                mma_tf32(d0, d1, d2, d3, a[kt][0], a[kt][1], a[kt][2], a[kt][3], bl0, bl1);
            }
            *(float2*)&s->xp[sub][e0][j0][c0] = make_float2(d0, d1);
            *(float2*)&s->xp[sub][e1][j1][c0] = make_float2(d2, d3);
        }
    }
}

// One bidirectional GRU layer: per phase, tensor-GEMM fills XP for 8 fwd +
// 8 bwd steps; the recurrence (lane u owns unit u of CH=3 chains) consumes
// XP from smem and runs only the 24-FFMA2 Wh part + gates on the FMA pipe.
template <int KT>
__device__ __forceinline__ void run_layer(Smem* s,
        const __half (*in)[EPADH], __half (*out)[EPADH], int tid)
{
    const int lane = tid & 31, warp = tid >> 5;
    const int u = tid & 15, grp = tid >> 4;
    const int dir = grp & 1, ebase = (grp >> 1) * 3;

    u64 whr[8], whz[8], whn[8];
#pragma unroll
    for (int k = 0; k < 8; k++) {
        whr[k] = s->wh[dir][u][k];
        whz[k] = s->wh[dir][16 + u][k];
        whn[k] = s->wh[dir][32 + u][k];
    }
    const float bnh = s->bNH[dir][u];
    float h[3] = {0.f, 0.f, 0.f};

    for (int sph = 0; sph < NPH; sph++) {
        gemm_phase<KT>(s, in, sph, warp, lane);
        __syncthreads();
#pragma unroll 1
        for (int jj = 0; jj < BLK; jj++) {
            const int t   = dir ? (63 - 8 * sph - jj) : (8 * sph + jj);
            const int row = dir ? (7 - jj) : jj;
#pragma unroll
            for (int c = 0; c < 3; c++) {
                const int e = ebase + c;
                const float* xr = &s->xp[dir][e][row][dir * 48];
                float fxr = xr[u], fxz = xr[16 + u], fxn = xr[32 + u];
                u64 ar = pack2(fxr, 0.f), az = pack2(fxz, 0.f), anh = pack2(bnh, 0.f);
#pragma unroll
                for (int k = 0; k < 4; k++) {
                    float h0 = __shfl_sync(0xffffffffu, h[c], 4 * k,     16);
                    float h1 = __shfl_sync(0xffffffffu, h[c], 4 * k + 1, 16);
                    float h2 = __shfl_sync(0xffffffffu, h[c], 4 * k + 2, 16);
                    float h3 = __shfl_sync(0xffffffffu, h[c], 4 * k + 3, 16);
                    u64 hv0 = pack2(h0, h1);
                    u64 hv1 = pack2(h2, h3);
                    ar  = ffma2(whr[2*k],   hv0, ar);
                    az  = ffma2(whz[2*k],   hv0, az);
                    anh = ffma2(whn[2*k],   hv0, anh);
                    ar  = ffma2(whr[2*k+1], hv1, ar);
                    az  = ffma2(whz[2*k+1], hv1, az);
                    anh = ffma2(whn[2*k+1], hv1, anh);
                }
                float r = sigm2(hadd(ar));
                float z = sigm2(hadd(az));
                float n = tanh2(fmaf(r, hadd(anh), fxn));
                h[c] = fmaf(z, h[c] - n, n);           // (1-z)*n + z*h
                out[e][t * 32 + dir * 16 + u] = __float2half_rn(h[c]);
            }
        }
        __syncthreads();
    }
}

extern "C" __global__ void __launch_bounds__(NTHR, 1)
fused_gru(const float* __restrict__ x,
          const float* __restrict__ Wi1, const float* __restrict__ Wh1,
          const float* __restrict__ bi1, const float* __restrict__ bh1,
          const float* __restrict__ Wi5, const float* __restrict__ Wh5,
          const float* __restrict__ bi5, const float* __restrict__ bh5,
          const float* __restrict__ Wc,  const float* __restrict__ bc,
          float* __restrict__ out)
{
    extern __shared__ __align__(16) unsigned char smraw[];
    Smem* s = reinterpret_cast<Smem*>(smraw);
    const int tid   = threadIdx.x;
    const int gbase = blockIdx.x * NB;

    // Stage layer-0 input x[B,T,3] into actA (cols 0..2; rest zero).
    // Tail CTA: out-of-range elems zero-filled; outputs guarded below.
    for (int i = tid; i < NB * T_ * 32; i += NTHR) {
        int e = i >> 11; int r2 = i & 2047; int t = r2 >> 5; int c = r2 & 31;
        float v = 0.f;
        if (c < 3 && gbase + e < B_)
            v = x[((size_t)(gbase + e)) * (T_ * 3) + t * 3 + c];
        s->actA[e][t * 32 + c] = __float2half_rn(v);
    }
    for (int i = tid; i < 128; i += NTHR) s->wcw[i >> 5][i & 31] = Wc[i];
    if (tid < 4) s->wcb[tid] = bc[tid];

    // Layer 0 (F=3 -> K=8, KT=1): actA -> actB
    stage_layer<3>(s, Wi1, Wh1, bi1, bh1, tid);
    __syncthreads();
    run_layer<1>(s, s->actA, s->actB, tid);
    __syncthreads();

    // Layers 1..5 (F=32, KT=4), ping-pong. Final output lands in actA.
#pragma unroll 1
    for (int l = 0; l < 5; l++) {
        stage_layer<32>(s, Wi5 + (size_t)l * 3072, Wh5 + (size_t)l * 1536,
                        bi5 + (size_t)l * 96, bh5 + (size_t)l * 96, tid);
        __syncthreads();
        if (l & 1) run_layer<4>(s, s->actA, s->actB, tid);
        else       run_layer<4>(s, s->actB, s->actA, tid);
        __syncthreads();
    }

    // Classifier + softmax from the fp16 tile.
    for (int i = tid; i < NB * T_; i += NTHR) {
        int e = i >> 6, t = i & 63;
        if (gbase + e >= B_) continue;
        const __half2* yp = (const __half2*)&s->actA[e][t * 32];
        float l0 = s->wcb[0], l1 = s->wcb[1], l2 = s->wcb[2], l3 = s->wcb[3];
#pragma unroll
        for (int k = 0; k < 16; k++) {
            float2 f = __half22float2(yp[k]);
            l0 = fmaf(f.x, s->wcw[0][2*k], fmaf(f.y, s->wcw[0][2*k+1], l0));
            l1 = fmaf(f.x, s->wcw[1][2*k], fmaf(f.y, s->wcw[1][2*k+1], l1));
            l2 = fmaf(f.x, s->wcw[2][2*k], fmaf(f.y, s->wcw[2][2*k+1], l2));
            l3 = fmaf(f.x, s->wcw[3][2*k], fmaf(f.y, s->wcw[3][2*k+1], l3));
        }
        float m  = fmaxf(fmaxf(l0, l1), fmaxf(l2, l3));
        float e0 = __expf(l0 - m), e1 = __expf(l1 - m);
        float e2 = __expf(l2 - m), e3 = __expf(l3 - m);
        float rs = __fdividef(1.f, e0 + e1 + e2 + e3);
        float4 o = make_float4(e0 * rs, e1 * rs, e2 * rs, e3 * rs);
        reinterpret_cast<float4*>(out)[((size_t)(gbase + e)) * T_ + t] = o;
    }
}

extern "C" void kernel_launch(void* const* d_in, const int* in_sizes, int n_in,
                              void* d_out, int out_size)
{
    const float* x   = (const float*)d_in[0];
    const float* Wi1 = (const float*)d_in[1];
    const float* Wh1 = (const float*)d_in[2];
    const float* bi1 = (const float*)d_in[3];
    const float* bh1 = (const float*)d_in[4];
    const float* Wi5 = (const float*)d_in[5];
    const float* Wh5 = (const float*)d_in[6];
    const float* bi5 = (const float*)d_in[7];
    const float* bh5 = (const float*)d_in[8];
    const float* Wc  = (const float*)d_in[9];
    const float* bc  = (const float*)d_in[10];
    float* out = (float*)d_out;

    static bool once = []() {
        cudaFuncSetAttribute(fused_gru,
            cudaFuncAttributeMaxDynamicSharedMemorySize, (int)sizeof(Smem));
        return true;
    }();
    (void)once;

    fused_gru<<<(B_ + NB - 1) / NB, NTHR, sizeof(Smem)>>>(
        x, Wi1, Wh1, bi1, bh1, Wi5, Wh5, bi5, bh5, Wc, bc, out);
}

// round 17
// speedup vs baseline: 3.4146x; 1.9182x over previous
#include <cuda_runtime.h>

#define B_    16384
#define T_    64
#define NB    4          // batch elems per CTA (8 groups: 4 elems x 2 dirs)
#define NTHR  128        // 8 groups x 16 lanes; 4 warps; 3 CTAs/SM -> 3 warps/SMSP
#define EPAD  2052       // floats per elem tile: 64*32 + pad, 16B-aligned

typedef unsigned long long u64;

#define L2E 1.4426950408889634f

// Small smem: activations + n-gate weight stream + biases. r/z weights live
// in per-thread registers (loaded from global once per layer).
// Weight-row strides padded (17 / 9 u64) so the 16 lanes of a group read 16
// DISTINCT banks (bank = 2u+2k resp. 18u+2k) — R15's 128B-stride rows put
// every lane on the same bank pair (16-way conflict, the 6.7ms failure).
struct __align__(16) Smem {
    u64   win[2][16][17];         // n-gate input weights  [dir][u][k-pair]
    u64   whn[2][16][9];          // n-gate recur weights  [dir][u][k-pair]
    float actA[NB][EPAD];
    float actB[NB][EPAD];
    float bR[2][16], bZ[2][16], bNX[2][16], bNH[2][16];
    float wcw[4][32];
    float wcb[4];
};

__device__ __forceinline__ u64 pack2(float lo, float hi) {
    u64 r; asm("mov.b64 %0, {%1, %2};" : "=l"(r) : "f"(lo), "f"(hi)); return r;
}
__device__ __forceinline__ void unpack2(u64 d, float& lo, float& hi) {
    asm("mov.b64 {%0, %1}, %2;" : "=f"(lo), "=f"(hi) : "l"(d));
}
__device__ __forceinline__ u64 ffma2(u64 a, u64 b, u64 c) {
    u64 d; asm("fma.rn.f32x2 %0, %1, %2, %3;" : "=l"(d) : "l"(a), "l"(b), "l"(c)); return d;
}
__device__ __forceinline__ float hadd(u64 v) {
    float lo, hi; unpack2(v, lo, hi); return lo + hi;
}
__device__ __forceinline__ float ex2(float x) {
    float r; asm("ex2.approx.ftz.f32 %0, %1;" : "=f"(r) : "f"(x)); return r;
}
__device__ __forceinline__ float rcp(float x) {
    float r; asm("rcp.approx.ftz.f32 %0, %1;" : "=f"(r) : "f"(x)); return r;
}
// s pre-scaled by log2e: sigmoid(x) = 1/(1+2^-s)
__device__ __forceinline__ float sigm2(float s) {
    return rcp(1.f + ex2(-s));
}
// s pre-scaled by 2*log2e: tanh(x) = sign * (1-2^-|s|)/(1+2^-|s|)
__device__ __forceinline__ float tanh2(float s) {
    float a = fabsf(s);
    float e = ex2(-a);
    float t = (1.f - e) * rcp(1.f + e);
    return copysignf(t, s);
}

// Stage n-gate weights (pre-scaled by 2*log2e) + biases into smem.
// r/z weights are NOT staged — each thread loads its own rows to registers.
template <int F, int KP>
__device__ __forceinline__ void stage_layer(Smem* s,
        const float* __restrict__ Wi, const float* __restrict__ Wh,
        const float* __restrict__ bi, const float* __restrict__ bh,
        int tid)
{
    const float sc = 2.f * L2E;
    for (int i = tid; i < 2 * 16 * KP; i += NTHR) {
        int d = i / (16 * KP); int r = i - d * (16 * KP);
        int uu = r / KP, kp = r - uu * KP;
        const float* w = Wi + ((size_t)d * 48 + 32 + uu) * F;
        float lo = w[2 * kp] * sc;
        float hi = (2 * kp + 1 < F) ? w[2 * kp + 1] * sc : 0.f;
        s->win[d][uu][kp] = pack2(lo, hi);
    }
    for (int i = tid; i < 2 * 16 * 8; i += NTHR) {
        int d = i >> 7; int r = i & 127;
        int uu = r >> 3, kp = r & 7;
        const float* w = Wh + ((size_t)d * 48 + 32 + uu) * 16;
        s->whn[d][uu][kp] = pack2(w[2 * kp] * sc, w[2 * kp + 1] * sc);
    }
    for (int i = tid; i < 2 * 16; i += NTHR) {
        int d = i >> 4, uu = i & 15;
        s->bR[d][uu]  = (bi[d * 48 + uu]      + bh[d * 48 + uu])      * L2E;
        s->bZ[d][uu]  = (bi[d * 48 + 16 + uu] + bh[d * 48 + 16 + uu]) * L2E;
        s->bNX[d][uu] = bi[d * 48 + 32 + uu] * sc;
        s->bNH[d][uu] = bh[d * 48 + 32 + uu] * sc;
    }
}

// One bidirectional GRU layer. Lane u of a 16-lane group owns hidden unit u
// of ONE chain. r/z weights in registers (loaded from global, scaled);
// n-gate weights streamed from smem (conflict-free padded rows, LDS.64).
// Recurrence h gathered via width-16 shfl. 3 warps/SMSP (3 CTAs/SM)
// interleave through each other's gate-tail stalls — same per-chain
// instruction count as the R11 champion, 3x the eligible warps.
template <int KP, int F>
__device__ __forceinline__ void run_layer(Smem* s,
        const float (*rd)[EPAD], float (*wr)[EPAD],
        const float* __restrict__ Wi, const float* __restrict__ Wh,
        int elem, int dir, int u)
{
    // r/z input weights: global -> regs, pre-scaled by log2e
    u64 wir[KP], wiz[KP];
    {
        const float* wrr = Wi + ((size_t)dir * 48 + u) * F;
        const float* wrz = Wi + ((size_t)dir * 48 + 16 + u) * F;
#pragma unroll
        for (int k = 0; k < KP; k++) {
            float rl = wrr[2 * k] * L2E;
            float rh = (2 * k + 1 < F) ? wrr[2 * k + 1] * L2E : 0.f;
            float zl = wrz[2 * k] * L2E;
            float zh = (2 * k + 1 < F) ? wrz[2 * k + 1] * L2E : 0.f;
            wir[k] = pack2(rl, rh);
            wiz[k] = pack2(zl, zh);
        }
    }
    // r/z recurrent weights: global -> regs, pre-scaled
    u64 whr[8], whz[8];
    {
        const float* whrp = Wh + ((size_t)dir * 48 + u) * 16;
        const float* whzp = Wh + ((size_t)dir * 48 + 16 + u) * 16;
#pragma unroll
        for (int k = 0; k < 8; k++) {
            whr[k] = pack2(whrp[2 * k] * L2E, whrp[2 * k + 1] * L2E);
            whz[k] = pack2(whzp[2 * k] * L2E, whzp[2 * k + 1] * L2E);
        }
    }
    const float br  = s->bR[dir][u],  bz  = s->bZ[dir][u];
    const float bnx = s->bNX[dir][u], bnh = s->bNH[dir][u];
    const u64* __restrict__ winp = &s->win[dir][u][0];   // conflict-free rows
    const u64* __restrict__ whnp = &s->whn[dir][u][0];
    const int wcol = dir * 16 + u;
    const int stp  = dir ? -1 : 1;

    float h;

    // x-gemm at time t (biases folded into accumulator init)
    auto xgemm = [&](int t, u64& ar, u64& az, u64& an) {
        ar = pack2(br, 0.f); az = pack2(bz, 0.f); an = pack2(bnx, 0.f);
        const ulonglong2* xp = (const ulonglong2*)&rd[elem][t * 32];
#pragma unroll
        for (int k = 0; k < KP / 2; k++) {
            ulonglong2 xv = xp[k];
            ar = ffma2(wir[2*k],     xv.x, ar);
            az = ffma2(wiz[2*k],     xv.x, az);
            an = ffma2(winp[2*k],    xv.x, an);
            ar = ffma2(wir[2*k+1],   xv.y, ar);
            az = ffma2(wiz[2*k+1],   xv.y, az);
            an = ffma2(winp[2*k+1],  xv.y, an);
        }
    };

    int t = dir ? (T_ - 1) : 0;

    // ---- peeled first step (h == 0, no recurrence) ----
    {
        u64 ar, az, an;
        xgemm(t, ar, az, an);
        float r = sigm2(hadd(ar));
        float z = sigm2(hadd(az));
        float n = tanh2(fmaf(r, bnh, hadd(an)));
        h = fmaf(-z, n, n);                      // (1-z)*n
        wr[elem][t * 32 + wcol] = h;
    }
    t += stp;

#pragma unroll 1
    for (int ti = 1; ti < T_; ++ti) {
        u64 ar, az, an;
        xgemm(t, ar, az, an);
        // recurrence: gather group's h via shfl (width 16), n-weights from smem
        u64 anh = pack2(bnh, 0.f);
#pragma unroll
        for (int k = 0; k < 4; k++) {
            u64 wn0 = whnp[2 * k];
            u64 wn1 = whnp[2 * k + 1];
            float h0 = __shfl_sync(0xffffffffu, h, 4 * k,     16);
            float h1 = __shfl_sync(0xffffffffu, h, 4 * k + 1, 16);
            float h2 = __shfl_sync(0xffffffffu, h, 4 * k + 2, 16);
            float h3 = __shfl_sync(0xffffffffu, h, 4 * k + 3, 16);
            u64 hv0 = pack2(h0, h1);
            u64 hv1 = pack2(h2, h3);
            ar  = ffma2(whr[2*k],   hv0, ar);
            az  = ffma2(whz[2*k],   hv0, az);
            anh = ffma2(wn0,        hv0, anh);
            ar  = ffma2(whr[2*k+1], hv1, ar);
            az  = ffma2(whz[2*k+1], hv1, az);
            anh = ffma2(wn1,        hv1, anh);
        }
        float r = sigm2(hadd(ar));
        float z = sigm2(hadd(az));
        float n = tanh2(fmaf(r, hadd(anh), hadd(an)));
        h = fmaf(z, h - n, n);                   // (1-z)*n + z*h
        wr[elem][t * 32 + wcol] = h;
        t += (ti == T_ - 1) ? 0 : stp;
    }
}

extern "C" __global__ void __launch_bounds__(NTHR, 3)
fused_gru(const float* __restrict__ x,
          const float* __restrict__ Wi1, const float* __restrict__ Wh1,
          const float* __restrict__ bi1, const float* __restrict__ bh1,
          const float* __restrict__ Wi5, const float* __restrict__ Wh5,
          const float* __restrict__ bi5, const float* __restrict__ bh5,
          const float* __restrict__ Wc,  const float* __restrict__ bc,
          float* __restrict__ out)
{
    extern __shared__ __align__(16) unsigned char smraw[];
    Smem* s = reinterpret_cast<Smem*>(smraw);

    const int tid   = threadIdx.x;
    const int u     = tid & 15;
    const int g     = tid >> 4;          // 8 groups; warp-uniform dir:
    const int dir   = g >> 2;            //  warps 0,1 -> dir 0; warps 2,3 -> dir 1
    const int elem  = g & 3;
    const int gbase = blockIdx.x * NB;

    // Stage layer-0 input x[B,T,3] into actA channels 0..3 (ch3 zeroed).
    for (int i = tid; i < NB * T_ * 4; i += NTHR) {
        int e = i >> 8; int r = i & 255; int t = r >> 2; int c = r & 3;
        float v = 0.f;
        if (c < 3)
            v = x[((size_t)(gbase + e)) * (T_ * 3) + t * 3 + c];
        s->actA[e][t * 32 + c] = v;
    }
    // Stage classifier weights once (unscaled).
    for (int i = tid; i < 128; i += NTHR) s->wcw[i >> 5][i & 31] = Wc[i];
    if (tid < 4) s->wcb[tid] = bc[tid];

    // Layer 0 (F=3, padded to 4 -> KP=2): actA -> actB
    stage_layer<3, 2>(s, Wi1, Wh1, bi1, bh1, tid);
    __syncthreads();
    run_layer<2, 3>(s, s->actA, s->actB, Wi1, Wh1, elem, dir, u);
    __syncthreads();

    // Layers 1..5 (F=32, KP=16), ping-pong. Final output lands in actA.
#pragma unroll 1
    for (int l = 0; l < 5; l++) {
        const float* Wi = Wi5 + (size_t)l * 3072;
        const float* Wh = Wh5 + (size_t)l * 1536;
        stage_layer<32, 16>(s, Wi, Wh,
                            bi5 + (size_t)l * 96, bh5 + (size_t)l * 96, tid);
        __syncthreads();
        if (l & 1) run_layer<16, 32>(s, s->actA, s->actB, Wi, Wh, elem, dir, u);
        else       run_layer<16, 32>(s, s->actB, s->actA, Wi, Wh, elem, dir, u);
        __syncthreads();
    }

    // Classifier + softmax, straight from smem to d_out (coalesced float4).
    for (int i = tid; i < NB * T_; i += NTHR) {
        int e = i >> 6, t = i & 63;
        const ulonglong2* yp = (const ulonglong2*)&s->actA[e][t * 32];
        const ulonglong2* w0 = (const ulonglong2*)&s->wcw[0][0];
        const ulonglong2* w1 = (const ulonglong2*)&s->wcw[1][0];
        const ulonglong2* w2 = (const ulonglong2*)&s->wcw[2][0];
        const ulonglong2* w3 = (const ulonglong2*)&s->wcw[3][0];
        u64 a0 = 0, a1 = 0, a2 = 0, a3 = 0;
#pragma unroll
        for (int k = 0; k < 8; k++) {
            ulonglong2 yv = yp[k];
            ulonglong2 c0 = w0[k], c1 = w1[k], c2 = w2[k], c3 = w3[k];
            a0 = ffma2(c0.x, yv.x, a0); a0 = ffma2(c0.y, yv.y, a0);
            a1 = ffma2(c1.x, yv.x, a1); a1 = ffma2(c1.y, yv.y, a1);
            a2 = ffma2(c2.x, yv.x, a2); a2 = ffma2(c2.y, yv.y, a2);
            a3 = ffma2(c3.x, yv.x, a3); a3 = ffma2(c3.y, yv.y, a3);
        }
        float l0 = hadd(a0) + s->wcb[0];
        float l1 = hadd(a1) + s->wcb[1];
        float l2 = hadd(a2) + s->wcb[2];
        float l3 = hadd(a3) + s->wcb[3];
        float m  = fmaxf(fmaxf(l0, l1), fmaxf(l2, l3));
        float e0 = __expf(l0 - m), e1 = __expf(l1 - m);
        float e2 = __expf(l2 - m), e3 = __expf(l3 - m);
        float rs = __fdividef(1.f, e0 + e1 + e2 + e3);
        float4 o = make_float4(e0 * rs, e1 * rs, e2 * rs, e3 * rs);
        reinterpret_cast<float4*>(out)[((size_t)(gbase + e)) * T_ + t] = o;
    }
}

extern "C" void kernel_launch(void* const* d_in, const int* in_sizes, int n_in,
                              void* d_out, int out_size)
{
    const float* x   = (const float*)d_in[0];
    const float* Wi1 = (const float*)d_in[1];
    const float* Wh1 = (const float*)d_in[2];
    const float* bi1 = (const float*)d_in[3];
    const float* bh1 = (const float*)d_in[4];
    const float* Wi5 = (const float*)d_in[5];
    const float* Wh5 = (const float*)d_in[6];
    const float* bi5 = (const float*)d_in[7];
    const float* bh5 = (const float*)d_in[8];
    const float* Wc  = (const float*)d_in[9];
    const float* bc  = (const float*)d_in[10];
    float* out = (float*)d_out;

    static bool once = []() {
        cudaFuncSetAttribute(fused_gru,
            cudaFuncAttributeMaxDynamicSharedMemorySize, (int)sizeof(Smem));
        return true;
    }();
    (void)once;

    fused_gru<<<B_ / NB, NTHR, sizeof(Smem)>>>(
        x, Wi1, Wh1, bi1, bh1, Wi5, Wh5, bi5, bh5, Wc, bc, out);
}